// round 17
// baseline (speedup 1.0000x reference)
#include <cuda_runtime.h>
#include <cstdint>
#include <cstddef>

#define T_STEPS 2048
#define BATCH   64
#define NIN     128
#define NHID    512
#define NOUT    64

#define CL      8            // ranks (column slices) per group
#define JT      64           // columns per CTA
#define BG      4            // batch rows per group
#define NGRP    (BATCH/BG)   // 16 groups
#define SGRID   (NGRP*CL)    // 128 CTAs
#define THR     64           // one thread per column; each owns all 4 rows

// Device-global scratch (load-time allocation)
__device__ float g_hall[(size_t)T_STEPS * BATCH * NHID];   // h_all fallback
__device__ float g_H[2][NGRP][NHID][BG];                   // h exchange [k][b]
__device__ int   g_flag[NGRP][CL];                         // per-rank release counters

// ---- L2-coherent / morally-strong access helpers ----
__device__ __forceinline__ float4 ldg_cv4(const float4* p) {
    float4 v;
    asm volatile("ld.global.cv.v4.f32 {%0,%1,%2,%3}, [%4];"
                 : "=f"(v.x), "=f"(v.y), "=f"(v.z), "=f"(v.w) : "l"(p) : "memory");
    return v;
}
__device__ __forceinline__ int ldg_acq_i(const int* p) {
    int v;
    asm volatile("ld.acquire.gpu.global.b32 %0, [%1];" : "=r"(v) : "l"(p) : "memory");
    return v;
}
__device__ __forceinline__ void red_rel_add(int* p, int v) {
    asm volatile("red.release.gpu.global.add.s32 [%0], %1;" :: "l"(p), "r"(v) : "memory");
}
__device__ __forceinline__ void stg_cg_v4(float* p, float a, float b, float c, float d) {
    asm volatile("st.global.cg.v4.f32 [%0], {%1,%2,%3,%4};"
                 :: "l"(p), "f"(a), "f"(b), "f"(c), "f"(d) : "memory");
}

// ---- XLA llvm_ir::EmitFastTanh, with_fma = true (VERBATIM from passing R15) ----
__device__ __forceinline__ float tanh_xla(float x) {
    const float kClamp = 7.99881172180175781f;
    float xc = fminf(fmaxf(x, -kClamp), kClamp);
    float x2 = __fmul_rn(xc, xc);
    float p = -2.76076847742355e-16f;                 // alpha_13
    p = fmaf(x2, p,  2.00018790482477e-13f);          // alpha_11
    p = fmaf(x2, p, -8.60467152213735e-11f);          // alpha_9
    p = fmaf(x2, p,  5.12229709037114e-08f);          // alpha_7
    p = fmaf(x2, p,  1.48572235717979e-05f);          // alpha_5
    p = fmaf(x2, p,  6.37261928875436e-04f);          // alpha_3
    p = fmaf(x2, p,  4.89352455891786e-03f);          // alpha_1
    p = __fmul_rn(xc, p);
    float q = 1.19825839466702e-06f;                  // beta_6
    q = fmaf(x2, q,  1.18534705686654e-04f);          // beta_4
    q = fmaf(x2, q,  2.26843463243900e-03f);          // beta_2
    q = fmaf(x2, q,  4.89352518554385e-03f);          // beta_0
    float r = __fdiv_rn(p, q);
    return (fabsf(x) < 0.0004f) ? x : r;
}

// ---------------- Kernel 0: reset exchange state (every replay) ----------------
__global__ void init_kernel() {
    int i = blockIdx.x * blockDim.x + threadIdx.x;
    if (i < 2 * NGRP * NHID * BG) ((float*)g_H)[i] = 0.f;   // BOTH parities
    if (i < NGRP * CL)            ((int*)g_flag)[i] = 0;    // counters -> 0
}

// ---------------- Kernel 1: recurrent scan ----------------
// 128 CTAs: group gid owns batch rows [4g,4g+4); rank owns cols [64r,64r+64)
// of W_hh/W_uh, SMEM-resident. Thread j (0..63) computes ALL 4 batch rows of
// column j0+j via the EXACT R13/R15 chains (identical values, identical order).
// Sync: per-rank counter flag[gid][r]; each thread red.release(+1) after its
// publish (own data stores ordered by ITS OWN release — no fence bridging).
// flag == 64*t  <=>  rank r fully published h_t and finished reading h_{t-1}.
__global__ void __launch_bounds__(THR, 1)
scan_kernel(const float* __restrict__ u,
            const float* __restrict__ W_uh,
            const float* __restrict__ W_hh,
            const float* __restrict__ b_hh,
            float* __restrict__ h_all) {
    extern __shared__ float smem[];
    float* Ws = smem;                    // [512][64] 128 KB  W_hh slice [k][j]
    float* Wu = Ws + NHID * JT;          // [128][64]  32 KB  W_uh slice [i][j]
    float* hS = Wu + NIN * JT;           // [512][4]    8 KB  h_t, [k][b]
    float* uL = hS + NHID * BG;          // [128][4]    2 KB  u_t, [i][b]

    const int tid  = threadIdx.x;
    const int rank = blockIdx.x & (CL - 1);
    const int gid  = blockIdx.x >> 3;
    const int b0   = gid * BG;
    const int j0   = rank * JT;

    // Resident weight slices (exact copies; coalesced global reads)
    for (int idx = tid; idx < NHID * JT; idx += THR)
        Ws[idx] = W_hh[(size_t)(idx >> 6) * NHID + j0 + (idx & 63)];
    for (int idx = tid; idx < NIN * JT; idx += THR)
        Wu[idx] = W_uh[(size_t)(idx >> 6) * NHID + j0 + (idx & 63)];
    __syncthreads();

    const int j = tid;                   // this thread's column
    const float bh = b_hh[j0 + j];
    const size_t row_off = (size_t)b0 * NHID + j0 + j;       // batch row 0 flat
    float* const slab0 = &g_H[0][gid][0][0];
    const size_t PSTR  = (size_t)NGRP * NHID * BG;           // parity stride
    float* const pub0  = &g_H[0][gid][j0 + j][0];            // [k][b], 16B slot

    float badv = 0.f;                    // garbage sentinel

    for (int t = 0; t < T_STEPS; t++) {
        const int cur = t & 1;
        const int nxt = cur ^ 1;

        // ---- A. stage u_t as uL[i][b]; dot_u hoisted before the wait ----
#pragma unroll
        for (int q = 0; q < 8; q++) {
            int idx = tid + q * THR;     // 0..511
            int i = idx >> 2, b = idx & 3;
            uL[idx] = u[((size_t)t * BATCH + b0 + b) * NIN + i];
        }
        __syncthreads();

        float u0 = 0.f, u1 = 0.f, u2 = 0.f, u3 = 0.f;
        {
            const float* wq = Wu + j;
#pragma unroll 8
            for (int i = 0; i < NIN; i++) {
                float4 uv = *(const float4*)(uL + i * BG);   // broadcast [i][0..3]
                float  w  = wq[i * JT];
                u0 = fmaf(uv.x, w, u0);
                u1 = fmaf(uv.y, w, u1);
                u2 = fmaf(uv.z, w, u2);
                u3 = fmaf(uv.w, w, u3);
            }
        }

        // ---- B. acquire: every rank's counter reached 64*t ----
        if (tid < CL) {
            const int* f = &g_flag[gid][tid];
            const int target = THR * t;
            while (ldg_acq_i(f) < target) { }
        }
        __syncthreads();                 // acquire observations propagate CTA-wide

        // ---- C. copy h_t slab (8 KB, [k][b]) L2 -> SMEM, with sentinel ----
        {
            const float4* src = (const float4*)(slab0 + (size_t)cur * PSTR);
            float4* dst = (float4*)hS;
#pragma unroll
            for (int q = 0; q < 8; q++) {
                float4 v = ldg_cv4(src + tid + q * THR);
                dst[tid + q * THR] = v;
                badv = fmaxf(badv, fmaxf(fmaxf(fabsf(v.x), fabsf(v.y)),
                                         fmaxf(fabsf(v.z), fabsf(v.w))));
            }
        }
        __syncthreads();

        // ---- D. dot_h: EXACT chains, k = 0..511 ascending, acc from 0 ----
        float a0 = 0.f, a1 = 0.f, a2 = 0.f, a3 = 0.f;
        {
            const float* wp = Ws + j;
#pragma unroll 8
            for (int k = 0; k < NHID; k++) {
                float4 h4 = *(const float4*)(hS + k * BG);   // broadcast [k][0..3]
                float  w  = wp[k * JT];                      // conflict-free
                a0 = fmaf(h4.x, w, a0);
                a1 = fmaf(h4.y, w, a1);
                a2 = fmaf(h4.z, w, a2);
                a3 = fmaf(h4.w, w, a3);
            }
        }

        // ---- E. combine (R13 order), tanh, store, publish, release ----
        float v0 = tanh_xla(__fadd_rn(a0, __fadd_rn(u0, bh)));
        float v1 = tanh_xla(__fadd_rn(a1, __fadd_rn(u1, bh)));
        float v2 = tanh_xla(__fadd_rn(a2, __fadd_rn(u2, bh)));
        float v3 = tanh_xla(__fadd_rn(a3, __fadd_rn(u3, bh)));

        float* ho = h_all + (size_t)t * (BATCH * NHID) + row_off;
        ho[0 * NHID] = v0;
        ho[1 * NHID] = v1;
        ho[2 * NHID] = v2;
        ho[3 * NHID] = v3;

        stg_cg_v4(pub0 + (size_t)nxt * PSTR, v0, v1, v2, v3);
        red_rel_add(&g_flag[gid][rank], 1);   // own stores ordered by own release
        // No bottom barrier: next step's spin on the OWN-rank counter (=64*(t+1))
        // is the intra-CTA barrier; uL/hS rewrites are gated by B's syncthreads.
    }

    // garbage sentinel: slab values are tanh outputs (|v| < 1) or init zeros.
    if (badv > 1.0001f)
        h_all[2] = 1.0e30f;
}

// ---------------- Kernel 2: logits (VERBATIM from passing R15) ----------------
__global__ __launch_bounds__(64) void logits_kernel(const float* __restrict__ h_last,
                                                    const float* __restrict__ W_hy,
                                                    const float* __restrict__ b_hy,
                                                    float* __restrict__ out) {
    __shared__ float hrow[NHID];
    const int bi = blockIdx.x;
    for (int k = threadIdx.x; k < NHID; k += blockDim.x)
        hrow[k] = h_last[(size_t)bi * NHID + k];
    __syncthreads();
    const int o = threadIdx.x;
    float acc = 0.f;
    for (int k = 0; k < NHID; k++)
        acc = fmaf(hrow[k], W_hy[(size_t)k * NOUT + o], acc);
    out[(size_t)bi * NOUT + o] = __fadd_rn(acc, b_hy[o]);
}

// ---------------- launch ----------------
extern "C" void kernel_launch(void* const* d_in, const int* in_sizes, int n_in,
                              void* d_out, int out_size) {
    const float *u = nullptr, *W_uh = nullptr, *W_hh = nullptr,
                *W_hy = nullptr, *b_hh = nullptr, *b_hy = nullptr;
    for (int i = 0; i < n_in; i++) {
        const float* p = (const float*)d_in[i];
        switch (in_sizes[i]) {
            case T_STEPS * BATCH * NIN: u    = p; break;  // 16777216
            case NIN * NHID:            W_uh = p; break;  // 65536
            case NHID * NHID:           W_hh = p; break;  // 262144
            case NHID * NOUT:           W_hy = p; break;  // 32768
            case NHID:                  b_hh = p; break;  // 512
            case NOUT:                  b_hy = p; break;  // 64
        }
    }
    if (!u || !W_uh || !W_hh || !W_hy || !b_hh || !b_hy) {
        u    = (const float*)d_in[0];
        W_uh = (const float*)d_in[1];
        W_hh = (const float*)d_in[2];
        W_hy = (const float*)d_in[3];
        b_hh = (const float*)d_in[4];
        b_hy = (const float*)d_in[5];
    }

    float* out    = (float*)d_out;
    float* logits = out;
    const long long full = (long long)BATCH * NOUT + (long long)T_STEPS * BATCH * NHID;
    float* h_all;
    if ((long long)out_size >= full) {
        h_all = out + BATCH * NOUT;
    } else {
        void* sym = nullptr;
        cudaGetSymbolAddress(&sym, g_hall);
        h_all = (float*)sym;
    }

    // 0) reset exchange buffers + counters (graph-replay safe)
    init_kernel<<<(2 * NGRP * NHID * BG + 255) / 256, 256>>>();

    // 1) recurrent scan: 128 CTAs, 64 threads, per-thread release counters
    {
        size_t shmem = (size_t)(NHID * JT + NIN * JT + NHID * BG + NIN * BG)
                       * sizeof(float);                   // 174080 B
        cudaFuncSetAttribute(scan_kernel,
                             cudaFuncAttributeMaxDynamicSharedMemorySize, (int)shmem);
        scan_kernel<<<SGRID, THR, shmem>>>(u, W_uh, W_hh, b_hh, h_all);
    }

    // 2) logits from h_{T-1}
    {
        const float* h_last = h_all + (size_t)(T_STEPS - 1) * BATCH * NHID;
        logits_kernel<<<BATCH, NOUT>>>(h_last, W_hy, b_hy, logits);
    }
}